// round 1
// baseline (speedup 1.0000x reference)
#include <cuda_runtime.h>
#include <cuda_bf16.h>

// Problem constants
#define B_   2
#define T_   4096
#define D_   768
#define DO_  256
#define H_   4
#define DH_  64
#define W1_  7
#define W2_  15
#define TP_  (T_ + 2*W1_)      // 4110 padded length
#define ROWS_ (B_ * TP_)        // 8220
#define NQV_ 512                // concat q(256) + v(256)

// Scratch (device globals — no allocation allowed)
__device__ float g_qv[ROWS_ * NQV_];    // [row][0:256]=q_pad, [256:512]=v_pad
__device__ float g_pos[W2_ * NQV_];     // [w][0:256]=pos_q,  [256:512]=pos_v

// ---------------------------------------------------------------------------
// Kernel 1: pos_q = pos_emb @ Wq.T ; pos_v = pos_emb @ Wv.T  (tiny)
// grid = 15 blocks, 256 threads
// ---------------------------------------------------------------------------
__global__ void pos_kernel(const float* __restrict__ pos_emb,
                           const float* __restrict__ Wq,
                           const float* __restrict__ Wv) {
    __shared__ float row[D_];
    int w = blockIdx.x;
    for (int i = threadIdx.x; i < D_; i += blockDim.x)
        row[i] = pos_emb[w * D_ + i];
    __syncthreads();
    const float4* r4 = (const float4*)row;
    for (int c = threadIdx.x; c < NQV_; c += blockDim.x) {
        const float* wr = (c < DO_) ? (Wq + (size_t)c * D_)
                                    : (Wv + (size_t)(c - DO_) * D_);
        const float4* w4 = (const float4*)wr;
        float s = 0.f;
        #pragma unroll 8
        for (int k = 0; k < D_ / 4; k++) {
            float4 a = r4[k], b = w4[k];
            s += a.x * b.x + a.y * b.y + a.z * b.z + a.w * b.w;
        }
        g_pos[w * NQV_ + c] = s;
    }
}

// ---------------------------------------------------------------------------
// Kernel 2: fused projection GEMM
//   g_qv[r][n] = pad_row(r) @ W[n].T + bias[n]
//   r in [0, 8220): b = r / 4110, tp = r % 4110; input row = inputs[b][tp-7]
//   if tp in [7, 4103), else zeros (pure bias).
//   W[n] = Wq[n] for n<256 else Wv[n-256]; bias likewise.
// 128x128x16 tiles, 256 threads, double-buffered smem, 8x8 per thread.
// ---------------------------------------------------------------------------
__global__ __launch_bounds__(256) void gemm_kernel(
    const float* __restrict__ inputs,
    const float* __restrict__ Wq, const float* __restrict__ bq,
    const float* __restrict__ Wv, const float* __restrict__ bv)
{
    __shared__ float As[2][16][132];   // [k][m], padded
    __shared__ float Bs[2][16][132];   // [k][n], padded

    const int tid = threadIdx.x;
    const int tx  = tid & 15;          // 0..15 (n dim)
    const int ty  = tid >> 4;          // 0..15 (m dim)
    const int m0  = blockIdx.x * 128;
    const int n0  = blockIdx.y * 128;

    // ---- A loader: thread owns row a_m, two float4's (cols a_f*4 .. a_f*4+7)
    const int a_m = tid >> 1;
    const int a_f = (tid & 1) * 2;
    const int r_a = m0 + a_m;
    int bb = r_a / TP_;
    int tp = r_a - bb * TP_;
    const bool a_valid = (r_a < ROWS_) && (tp >= W1_) && (tp < W1_ + T_);
    const float* a_src = a_valid
        ? inputs + ((size_t)bb * T_ + (tp - W1_)) * D_
        : inputs;   // dummy (guarded)

    // ---- B loader: thread owns W row b_n, two float4's
    const int b_n = tid >> 1;
    const int b_f = (tid & 1) * 2;
    const int ng  = n0 + b_n;
    const float* b_src = (ng < DO_) ? Wq + (size_t)ng * D_
                                    : Wv + (size_t)(ng - DO_) * D_;

    float acc[8][8];
    #pragma unroll
    for (int i = 0; i < 8; i++)
        #pragma unroll
        for (int j = 0; j < 8; j++) acc[i][j] = 0.f;

    const int NK = D_ / 16;   // 48 chunks

    // prologue: load chunk 0 into buffer 0
    {
        float4 av0 = make_float4(0,0,0,0), av1 = make_float4(0,0,0,0);
        if (a_valid) {
            av0 = *(const float4*)(a_src + a_f * 4);
            av1 = *(const float4*)(a_src + a_f * 4 + 4);
        }
        float4 bv0 = *(const float4*)(b_src + b_f * 4);
        float4 bv1 = *(const float4*)(b_src + b_f * 4 + 4);
        As[0][a_f*4+0][a_m] = av0.x; As[0][a_f*4+1][a_m] = av0.y;
        As[0][a_f*4+2][a_m] = av0.z; As[0][a_f*4+3][a_m] = av0.w;
        As[0][a_f*4+4][a_m] = av1.x; As[0][a_f*4+5][a_m] = av1.y;
        As[0][a_f*4+6][a_m] = av1.z; As[0][a_f*4+7][a_m] = av1.w;
        Bs[0][b_f*4+0][b_n] = bv0.x; Bs[0][b_f*4+1][b_n] = bv0.y;
        Bs[0][b_f*4+2][b_n] = bv0.z; Bs[0][b_f*4+3][b_n] = bv0.w;
        Bs[0][b_f*4+4][b_n] = bv1.x; Bs[0][b_f*4+5][b_n] = bv1.y;
        Bs[0][b_f*4+6][b_n] = bv1.z; Bs[0][b_f*4+7][b_n] = bv1.w;
    }
    __syncthreads();

    int buf = 0;
    for (int c = 0; c < NK; c++) {
        float4 av0, av1, bv0, bv1;
        const bool more = (c + 1 < NK);
        if (more) {
            const int kk = (c + 1) * 16;
            av0 = make_float4(0,0,0,0); av1 = make_float4(0,0,0,0);
            if (a_valid) {
                av0 = *(const float4*)(a_src + kk + a_f * 4);
                av1 = *(const float4*)(a_src + kk + a_f * 4 + 4);
            }
            bv0 = *(const float4*)(b_src + kk + b_f * 4);
            bv1 = *(const float4*)(b_src + kk + b_f * 4 + 4);
        }

        #pragma unroll
        for (int k = 0; k < 16; k++) {
            float4 a0 = *(const float4*)&As[buf][k][ty * 4];
            float4 a1 = *(const float4*)&As[buf][k][64 + ty * 4];
            float4 b0 = *(const float4*)&Bs[buf][k][tx * 4];
            float4 b1 = *(const float4*)&Bs[buf][k][64 + tx * 4];
            float ar[8] = {a0.x,a0.y,a0.z,a0.w,a1.x,a1.y,a1.z,a1.w};
            float br[8] = {b0.x,b0.y,b0.z,b0.w,b1.x,b1.y,b1.z,b1.w};
            #pragma unroll
            for (int i = 0; i < 8; i++)
                #pragma unroll
                for (int j = 0; j < 8; j++)
                    acc[i][j] += ar[i] * br[j];
        }

        if (more) {
            int nb = buf ^ 1;
            As[nb][a_f*4+0][a_m] = av0.x; As[nb][a_f*4+1][a_m] = av0.y;
            As[nb][a_f*4+2][a_m] = av0.z; As[nb][a_f*4+3][a_m] = av0.w;
            As[nb][a_f*4+4][a_m] = av1.x; As[nb][a_f*4+5][a_m] = av1.y;
            As[nb][a_f*4+6][a_m] = av1.z; As[nb][a_f*4+7][a_m] = av1.w;
            Bs[nb][b_f*4+0][b_n] = bv0.x; Bs[nb][b_f*4+1][b_n] = bv0.y;
            Bs[nb][b_f*4+2][b_n] = bv0.z; Bs[nb][b_f*4+3][b_n] = bv0.w;
            Bs[nb][b_f*4+4][b_n] = bv1.x; Bs[nb][b_f*4+5][b_n] = bv1.y;
            Bs[nb][b_f*4+6][b_n] = bv1.z; Bs[nb][b_f*4+7][b_n] = bv1.w;
            __syncthreads();
            buf = nb;
        }
    }

    // bias (region is constant per n0 block since n0+127 < next region)
    const float* bias_ptr = (n0 < DO_) ? (bq + n0) : (bv + (n0 - DO_));
    float bias0[4], bias1[4];
    #pragma unroll
    for (int j = 0; j < 4; j++) {
        bias0[j] = bias_ptr[tx * 4 + j];
        bias1[j] = bias_ptr[64 + tx * 4 + j];
    }

    #pragma unroll
    for (int i = 0; i < 8; i++) {
        int mrow = (i < 4) ? (ty * 4 + i) : (64 + ty * 4 + (i - 4));
        int r = m0 + mrow;
        if (r < ROWS_) {
            float4 o0, o1;
            o0.x = acc[i][0] + bias0[0]; o0.y = acc[i][1] + bias0[1];
            o0.z = acc[i][2] + bias0[2]; o0.w = acc[i][3] + bias0[3];
            o1.x = acc[i][4] + bias1[0]; o1.y = acc[i][5] + bias1[1];
            o1.z = acc[i][6] + bias1[2]; o1.w = acc[i][7] + bias1[3];
            float* dst = g_qv + (size_t)r * NQV_ + n0;
            *(float4*)(dst + tx * 4)      = o0;
            *(float4*)(dst + 64 + tx * 4) = o1;
        }
    }
}

// ---------------------------------------------------------------------------
// Kernel 3: sliding-window score/context.
// Block handles 64 consecutive t for one (b, h). Smem holds padded rows
// [t0, t0+78) of the head slice of q_pad (as k source) and v_pad, plus pos.
// One warp per t (8 warps x 8 t each). Lane l owns dims {l, l+32}.
// ---------------------------------------------------------------------------
__global__ __launch_bounds__(256) void attn_kernel(float* __restrict__ out) {
    __shared__ float ks[78 * 64];
    __shared__ float vs[78 * 64];
    __shared__ float pq[W2_ * 64];
    __shared__ float pv[W2_ * 64];

    const int bx    = blockIdx.x;          // 0..511
    const int chunk = bx & 63;
    const int h     = (bx >> 6) & 3;
    const int b     = bx >> 8;
    const int t0    = chunk * 64;
    const int tid   = threadIdx.x;

    const size_t base_row = (size_t)b * TP_ + t0;   // padded coords

    // load k/v head slices (78 rows x 64 floats, float4 = 16 per row)
    for (int idx = tid; idx < 78 * 16; idx += 256) {
        int row = idx >> 4, c4 = idx & 15;
        const float* src = g_qv + (base_row + row) * NQV_ + h * DH_;
        ((float4*)ks)[row * 16 + c4] = ((const float4*)src)[c4];
        ((float4*)vs)[row * 16 + c4] = ((const float4*)(src + DO_))[c4];
    }
    for (int idx = tid; idx < W2_ * 16; idx += 256) {
        int row = idx >> 4, c4 = idx & 15;
        const float* src = g_pos + (size_t)row * NQV_ + h * DH_;
        ((float4*)pq)[row * 16 + c4] = ((const float4*)src)[c4];
        ((float4*)pv)[row * 16 + c4] = ((const float4*)(src + DO_))[c4];
    }
    __syncthreads();

    const int warp = tid >> 5;
    const int lane = tid & 31;

    for (int j = 0; j < 8; j++) {
        const int tl = warp * 8 + j;   // 0..63
        const float q0 = ks[(tl + W1_) * 64 + lane];
        const float q1 = ks[(tl + W1_) * 64 + lane + 32];

        float p[W2_];
        #pragma unroll
        for (int w = 0; w < W2_; w++) {
            float k0 = ks[(tl + w) * 64 + lane]      + pq[w * 64 + lane];
            float k1 = ks[(tl + w) * 64 + lane + 32] + pq[w * 64 + lane + 32];
            p[w] = q0 * k0 + q1 * k1;
        }
        // batched butterfly reductions (independent chains -> ILP)
        #pragma unroll
        for (int off = 16; off >= 1; off >>= 1) {
            #pragma unroll
            for (int w = 0; w < W2_; w++)
                p[w] += __shfl_xor_sync(0xffffffffu, p[w], off);
        }
        float a0 = 0.f, a1 = 0.f;
        #pragma unroll
        for (int w = 0; w < W2_; w++) {
            a0 += p[w] * (vs[(tl + w) * 64 + lane]      + pv[w * 64 + lane]);
            a1 += p[w] * (vs[(tl + w) * 64 + lane + 32] + pv[w * 64 + lane + 32]);
        }
        const int t = t0 + tl;
        float* dst = out + ((size_t)b * T_ + t) * DO_ + h * DH_;
        dst[lane]      = a0;
        dst[lane + 32] = a1;
    }
}

// ---------------------------------------------------------------------------
extern "C" void kernel_launch(void* const* d_in, const int* in_sizes, int n_in,
                              void* d_out, int out_size) {
    const float* inputs  = (const float*)d_in[0];
    const float* Wq      = (const float*)d_in[1];
    const float* bq      = (const float*)d_in[2];
    const float* Wv      = (const float*)d_in[3];
    const float* bv      = (const float*)d_in[4];
    const float* pos_emb = (const float*)d_in[5];
    float* out = (float*)d_out;

    pos_kernel<<<W2_, 256>>>(pos_emb, Wq, Wv);

    dim3 ggrid((ROWS_ + 127) / 128, NQV_ / 128);
    gemm_kernel<<<ggrid, 256>>>(inputs, Wq, bq, Wv, bv);

    attn_kernel<<<B_ * H_ * (T_ / 64), 256>>>(out);
}

// round 2
// speedup vs baseline: 1.2922x; 1.2922x over previous
#include <cuda_runtime.h>
#include <cuda_bf16.h>

// Problem constants
#define B_   2
#define T_   4096
#define D_   768
#define DO_  256
#define H_   4
#define DH_  64
#define W1_  7
#define W2_  15
#define TP_  (T_ + 2*W1_)       // 4110 padded length
#define ROWS_ (B_ * TP_)        // 8220
#define MTOT_ (ROWS_ + W2_)     // 8235 (pos rows folded in)
#define NQV_ 512                // concat q(256) + v(256)

// Scratch (device globals — no allocation allowed)
__device__ float g_qv[ROWS_ * NQV_];    // [row][0:256]=q_pad, [256:512]=v_pad
__device__ float g_pos[W2_ * NQV_];     // [w][0:256]=pos_q,  [256:512]=pos_v

typedef unsigned long long ull;

__device__ __forceinline__ ull pack2(float lo, float hi) {
    ull r;
    asm("mov.b64 %0, {%1, %2};" : "=l"(r) : "f"(lo), "f"(hi));
    return r;
}
__device__ __forceinline__ void unpack2(ull v, float& lo, float& hi) {
    asm("mov.b64 {%0, %1}, %2;" : "=f"(lo), "=f"(hi) : "l"(v));
}
#define FFMA2(acc, a, b) \
    asm("fma.rn.f32x2 %0, %1, %2, %0;" : "+l"(acc) : "l"(a), "l"(b))

// ---------------------------------------------------------------------------
// Fused projection GEMM (pos rows folded in as rows [8220, 8235)):
//   rows r < 8220:  g_qv[r][n] = pad_row(r) @ W[n].T + bias[n]
//                   (b = r/4110, tp = r%4110; input row inputs[b][tp-7] when
//                    tp in [7, 4103), else zeros -> pure bias)
//   rows r >= 8220: g_pos[r-8220][n] = pos_emb[r-8220] @ W[n].T   (no bias)
//   W[n] = Wq[n] for n<256 else Wv[n-256].
// 128x128x16 tiles, 256 threads, double-buffered smem, 8x8 per thread,
// inner product via packed fma.rn.f32x2 (pairs along M).
// ---------------------------------------------------------------------------
__global__ __launch_bounds__(256) void gemm_kernel(
    const float* __restrict__ inputs,
    const float* __restrict__ Wq, const float* __restrict__ bq,
    const float* __restrict__ Wv, const float* __restrict__ bv,
    const float* __restrict__ pos_emb)
{
    __shared__ float As[2][16][132];   // [k][m], padded
    __shared__ float Bs[2][16][132];   // [k][n], padded

    const int tid = threadIdx.x;
    const int tx  = tid & 15;          // 0..15 (n dim)
    const int ty  = tid >> 4;          // 0..15 (m dim)
    const int m0  = blockIdx.x * 128;
    const int n0  = blockIdx.y * 128;

    // ---- A loader: thread owns row a_m, 8 floats (cols a_f*4 .. a_f*4+7)
    const int a_m = tid >> 1;
    const int a_f = (tid & 1) * 2;
    const int r_a = m0 + a_m;
    int bb = r_a / TP_;
    int tp = r_a - bb * TP_;
    bool a_valid;
    const float* a_src;
    if (r_a < ROWS_) {
        a_valid = (tp >= W1_) && (tp < W1_ + T_);
        a_src = a_valid ? inputs + ((size_t)bb * T_ + (tp - W1_)) * D_
                        : inputs;                 // dummy (guarded)
    } else if (r_a < MTOT_) {
        a_valid = true;
        a_src = pos_emb + (size_t)(r_a - ROWS_) * D_;
    } else {
        a_valid = false;
        a_src = inputs;
    }

    // ---- B loader: thread owns W row b_n, 8 floats
    const int b_n = tid >> 1;
    const int b_f = (tid & 1) * 2;
    const int ng  = n0 + b_n;
    const float* b_src = (ng < DO_) ? Wq + (size_t)ng * D_
                                    : Wv + (size_t)(ng - DO_) * D_;

    // packed accumulators: acc2[p][j], p = M-pair (4 pairs = 8 rows), j = 8 N
    ull acc2[4][8];
    const ull zz = 0ull;
    #pragma unroll
    for (int p = 0; p < 4; p++)
        #pragma unroll
        for (int j = 0; j < 8; j++) acc2[p][j] = zz;

    const int NK = D_ / 16;   // 48 chunks

    // prologue: load chunk 0 into buffer 0
    {
        float4 av0 = make_float4(0,0,0,0), av1 = make_float4(0,0,0,0);
        if (a_valid) {
            av0 = *(const float4*)(a_src + a_f * 4);
            av1 = *(const float4*)(a_src + a_f * 4 + 4);
        }
        float4 bv0 = *(const float4*)(b_src + b_f * 4);
        float4 bv1 = *(const float4*)(b_src + b_f * 4 + 4);
        As[0][a_f*4+0][a_m] = av0.x; As[0][a_f*4+1][a_m] = av0.y;
        As[0][a_f*4+2][a_m] = av0.z; As[0][a_f*4+3][a_m] = av0.w;
        As[0][a_f*4+4][a_m] = av1.x; As[0][a_f*4+5][a_m] = av1.y;
        As[0][a_f*4+6][a_m] = av1.z; As[0][a_f*4+7][a_m] = av1.w;
        Bs[0][b_f*4+0][b_n] = bv0.x; Bs[0][b_f*4+1][b_n] = bv0.y;
        Bs[0][b_f*4+2][b_n] = bv0.z; Bs[0][b_f*4+3][b_n] = bv0.w;
        Bs[0][b_f*4+4][b_n] = bv1.x; Bs[0][b_f*4+5][b_n] = bv1.y;
        Bs[0][b_f*4+6][b_n] = bv1.z; Bs[0][b_f*4+7][b_n] = bv1.w;
    }
    __syncthreads();

    int buf = 0;
    for (int c = 0; c < NK; c++) {
        float4 av0, av1, bv0, bv1;
        const bool more = (c + 1 < NK);
        if (more) {
            const int kk = (c + 1) * 16;
            av0 = make_float4(0,0,0,0); av1 = make_float4(0,0,0,0);
            if (a_valid) {
                av0 = *(const float4*)(a_src + kk + a_f * 4);
                av1 = *(const float4*)(a_src + kk + a_f * 4 + 4);
            }
            bv0 = *(const float4*)(b_src + kk + b_f * 4);
            bv1 = *(const float4*)(b_src + kk + b_f * 4 + 4);
        }

        #pragma unroll
        for (int k = 0; k < 16; k++) {
            // A pairs along M: two 16B loads give 4 packed f32x2 values
            ulonglong2 a00 = *(const ulonglong2*)&As[buf][k][ty * 4];
            ulonglong2 a01 = *(const ulonglong2*)&As[buf][k][64 + ty * 4];
            float4 b0 = *(const float4*)&Bs[buf][k][tx * 4];
            float4 b1 = *(const float4*)&Bs[buf][k][64 + tx * 4];
            ull a2[4] = {a00.x, a00.y, a01.x, a01.y};
            ull bd[8];
            bd[0] = pack2(b0.x, b0.x); bd[1] = pack2(b0.y, b0.y);
            bd[2] = pack2(b0.z, b0.z); bd[3] = pack2(b0.w, b0.w);
            bd[4] = pack2(b1.x, b1.x); bd[5] = pack2(b1.y, b1.y);
            bd[6] = pack2(b1.z, b1.z); bd[7] = pack2(b1.w, b1.w);
            #pragma unroll
            for (int p = 0; p < 4; p++)
                #pragma unroll
                for (int j = 0; j < 8; j++)
                    FFMA2(acc2[p][j], a2[p], bd[j]);
        }

        if (more) {
            int nb = buf ^ 1;
            As[nb][a_f*4+0][a_m] = av0.x; As[nb][a_f*4+1][a_m] = av0.y;
            As[nb][a_f*4+2][a_m] = av0.z; As[nb][a_f*4+3][a_m] = av0.w;
            As[nb][a_f*4+4][a_m] = av1.x; As[nb][a_f*4+5][a_m] = av1.y;
            As[nb][a_f*4+6][a_m] = av1.z; As[nb][a_f*4+7][a_m] = av1.w;
            Bs[nb][b_f*4+0][b_n] = bv0.x; Bs[nb][b_f*4+1][b_n] = bv0.y;
            Bs[nb][b_f*4+2][b_n] = bv0.z; Bs[nb][b_f*4+3][b_n] = bv0.w;
            Bs[nb][b_f*4+4][b_n] = bv1.x; Bs[nb][b_f*4+5][b_n] = bv1.y;
            Bs[nb][b_f*4+6][b_n] = bv1.z; Bs[nb][b_f*4+7][b_n] = bv1.w;
            __syncthreads();
            buf = nb;
        }
    }

    // unpack accumulators: acc[i][j], i = 0..7 M rows (pairs interleaved)
    float acc[8][8];
    #pragma unroll
    for (int p = 0; p < 4; p++)
        #pragma unroll
        for (int j = 0; j < 8; j++)
            unpack2(acc2[p][j], acc[p * 2][j], acc[p * 2 + 1][j]);

    // bias (n-region constant per block: 128 | 256 boundary aligned)
    const float* bias_ptr = (n0 < DO_) ? (bq + n0) : (bv + (n0 - DO_));
    float bias0[4], bias1[4];
    #pragma unroll
    for (int j = 0; j < 4; j++) {
        bias0[j] = bias_ptr[tx * 4 + j];
        bias1[j] = bias_ptr[64 + tx * 4 + j];
    }

    #pragma unroll
    for (int i = 0; i < 8; i++) {
        // pair p=i/2 covers rows {ty*4 + 2*(p%2), +1} in group p/2
        int p = i >> 1;
        int mrow = (p < 2) ? (ty * 4 + (p & 1) * 2 + (i & 1))
                           : (64 + ty * 4 + ((p - 2) & 1) * 2 + (i & 1));
        int r = m0 + mrow;
        if (r < ROWS_) {
            float4 o0, o1;
            o0.x = acc[i][0] + bias0[0]; o0.y = acc[i][1] + bias0[1];
            o0.z = acc[i][2] + bias0[2]; o0.w = acc[i][3] + bias0[3];
            o1.x = acc[i][4] + bias1[0]; o1.y = acc[i][5] + bias1[1];
            o1.z = acc[i][6] + bias1[2]; o1.w = acc[i][7] + bias1[3];
            float* dst = g_qv + (size_t)r * NQV_ + n0;
            *(float4*)(dst + tx * 4)      = o0;
            *(float4*)(dst + 64 + tx * 4) = o1;
        } else if (r < MTOT_) {
            float4 o0, o1;
            o0.x = acc[i][0]; o0.y = acc[i][1];
            o0.z = acc[i][2]; o0.w = acc[i][3];
            o1.x = acc[i][4]; o1.y = acc[i][5];
            o1.z = acc[i][6]; o1.w = acc[i][7];
            float* dst = g_pos + (size_t)(r - ROWS_) * NQV_ + n0;
            *(float4*)(dst + tx * 4)      = o0;
            *(float4*)(dst + 64 + tx * 4) = o1;
        }
    }
}

// ---------------------------------------------------------------------------
// Sliding-window score/context.
// Block handles 64 consecutive t for one (b, h). Smem holds padded rows
// [t0, t0+78) of the head slice of q_pad (as k source) and v_pad, plus pos.
// One warp per t (8 warps x 8 t each). Lane l owns dims {l, l+32}.
// ---------------------------------------------------------------------------
__global__ __launch_bounds__(256) void attn_kernel(float* __restrict__ out) {
    __shared__ float ks[78 * 64];
    __shared__ float vs[78 * 64];
    __shared__ float pq[W2_ * 64];
    __shared__ float pv[W2_ * 64];

    const int bx    = blockIdx.x;          // 0..511
    const int chunk = bx & 63;
    const int h     = (bx >> 6) & 3;
    const int b     = bx >> 8;
    const int t0    = chunk * 64;
    const int tid   = threadIdx.x;

    const size_t base_row = (size_t)b * TP_ + t0;   // padded coords

    // load k/v head slices (78 rows x 64 floats, float4 = 16 per row)
    for (int idx = tid; idx < 78 * 16; idx += 256) {
        int row = idx >> 4, c4 = idx & 15;
        const float* src = g_qv + (base_row + row) * NQV_ + h * DH_;
        ((float4*)ks)[row * 16 + c4] = ((const float4*)src)[c4];
        ((float4*)vs)[row * 16 + c4] = ((const float4*)(src + DO_))[c4];
    }
    for (int idx = tid; idx < W2_ * 16; idx += 256) {
        int row = idx >> 4, c4 = idx & 15;
        const float* src = g_pos + (size_t)row * NQV_ + h * DH_;
        ((float4*)pq)[row * 16 + c4] = ((const float4*)src)[c4];
        ((float4*)pv)[row * 16 + c4] = ((const float4*)(src + DO_))[c4];
    }
    __syncthreads();

    const int warp = tid >> 5;
    const int lane = tid & 31;

    for (int j = 0; j < 8; j++) {
        const int tl = warp * 8 + j;   // 0..63
        const float q0 = ks[(tl + W1_) * 64 + lane];
        const float q1 = ks[(tl + W1_) * 64 + lane + 32];

        float p[W2_];
        #pragma unroll
        for (int w = 0; w < W2_; w++) {
            float k0 = ks[(tl + w) * 64 + lane]      + pq[w * 64 + lane];
            float k1 = ks[(tl + w) * 64 + lane + 32] + pq[w * 64 + lane + 32];
            p[w] = q0 * k0 + q1 * k1;
        }
        // batched butterfly reductions (independent chains -> ILP)
        #pragma unroll
        for (int off = 16; off >= 1; off >>= 1) {
            #pragma unroll
            for (int w = 0; w < W2_; w++)
                p[w] += __shfl_xor_sync(0xffffffffu, p[w], off);
        }
        float a0 = 0.f, a1 = 0.f;
        #pragma unroll
        for (int w = 0; w < W2_; w++) {
            a0 += p[w] * (vs[(tl + w) * 64 + lane]      + pv[w * 64 + lane]);
            a1 += p[w] * (vs[(tl + w) * 64 + lane + 32] + pv[w * 64 + lane + 32]);
        }
        const int t = t0 + tl;
        float* dst = out + ((size_t)b * T_ + t) * DO_ + h * DH_;
        dst[lane]      = a0;
        dst[lane + 32] = a1;
    }
}

// ---------------------------------------------------------------------------
extern "C" void kernel_launch(void* const* d_in, const int* in_sizes, int n_in,
                              void* d_out, int out_size) {
    const float* inputs  = (const float*)d_in[0];
    const float* Wq      = (const float*)d_in[1];
    const float* bq      = (const float*)d_in[2];
    const float* Wv      = (const float*)d_in[3];
    const float* bv      = (const float*)d_in[4];
    const float* pos_emb = (const float*)d_in[5];
    float* out = (float*)d_out;

    dim3 ggrid((MTOT_ + 127) / 128, NQV_ / 128);
    gemm_kernel<<<ggrid, 256>>>(inputs, Wq, bq, Wv, bv, pos_emb);

    attn_kernel<<<B_ * H_ * (T_ / 64), 256>>>(out);
}

// round 4
// speedup vs baseline: 1.8989x; 1.4695x over previous
#include <cuda_runtime.h>
#include <cuda_bf16.h>
#include <cstdint>

// Problem constants
#define B_   2
#define T_   4096
#define D_   768
#define DO_  256
#define H_   4
#define DH_  64
#define W1_  7
#define W2_  15
#define TP_  (T_ + 2*W1_)       // 4110 padded length
#define ROWS_ (B_ * TP_)        // 8220
#define MTOT_ (ROWS_ + W2_)     // 8235 (pos rows folded in)
#define NQV_ 512                // concat q(256) + v(256)

#define CHUNK_  32              // original-k per pipeline chunk
#define NCHUNK_ (D_ / CHUNK_)   // 24
#define MT_ 128
#define NT_ 128
#define ASTRIDE_ 40             // bf16 elems per smem row (32 + 8 pad) -> conflict-free

// Scratch (device globals — no allocation allowed)
__device__ float g_qv[ROWS_ * NQV_];          // [row][0:256]=q_pad, [256:512]=v_pad
__device__ float g_pos[W2_ * NQV_];           // [w][0:256]=pos_q,  [256:512]=pos_v
__device__ __nv_bfloat16 g_bhi[NQV_ * D_];    // weight hi split, [n][k]
__device__ __nv_bfloat16 g_blo[NQV_ * D_];    // weight lo split

// ---------------------------------------------------------------------------
// mma.sync m16n8k16 bf16 (HMMA path — valid on plain sm_103 target)
// ---------------------------------------------------------------------------
__device__ __forceinline__ void mma_bf16(float* d, const uint32_t* a,
                                         const uint32_t* b) {
    asm volatile(
        "mma.sync.aligned.m16n8k16.row.col.f32.bf16.bf16.f32 "
        "{%0,%1,%2,%3}, {%4,%5,%6,%7}, {%8,%9}, {%0,%1,%2,%3};"
        : "+f"(d[0]), "+f"(d[1]), "+f"(d[2]), "+f"(d[3])
        : "r"(a[0]), "r"(a[1]), "r"(a[2]), "r"(a[3]), "r"(b[0]), "r"(b[1]));
}

// ---------------------------------------------------------------------------
// Prep: split weights into bf16 hi/lo.  W[n] = Wq[n] (n<256) else Wv[n-256].
// ---------------------------------------------------------------------------
__global__ void bprep_kernel(const float* __restrict__ Wq,
                             const float* __restrict__ Wv) {
    int i = blockIdx.x * blockDim.x + threadIdx.x;
    if (i < NQV_ * D_) {
        int n = i / D_, k = i - n * D_;
        float x = (n < DO_) ? Wq[(size_t)n * D_ + k] : Wv[(size_t)(n - DO_) * D_ + k];
        __nv_bfloat16 h = __float2bfloat16(x);
        float r = x - __bfloat162float(h);
        g_bhi[i] = h;
        g_blo[i] = __float2bfloat16(r);
    }
}

// ---------------------------------------------------------------------------
// GEMM [MTOT_, 768] x [512, 768]^T via 3-term bf16 split on HMMA.
// CTA: 128x128, 8 warps (2 Mwarps x 4 Nwarps), warp does 64x32 via 4x4
// m16n8k16 tiles. Single-buffer smem, chunk k=32, 2 CTAs/SM for overlap.
// ---------------------------------------------------------------------------
__global__ __launch_bounds__(256, 2) void gemm_mma_kernel(
    const float* __restrict__ inputs,
    const float* __restrict__ bq, const float* __restrict__ bv,
    const float* __restrict__ pos_emb)
{
    __shared__ __align__(16) __nv_bfloat16 sAh[MT_ * ASTRIDE_];
    __shared__ __align__(16) __nv_bfloat16 sAl[MT_ * ASTRIDE_];
    __shared__ __align__(16) __nv_bfloat16 sBh[NT_ * ASTRIDE_];
    __shared__ __align__(16) __nv_bfloat16 sBl[NT_ * ASTRIDE_];
    __shared__ float bias_s[NT_];

    const int tid  = threadIdx.x;
    const int wid  = tid >> 5;
    const int lane = tid & 31;
    const int m0   = blockIdx.x * MT_;
    const int n0   = blockIdx.y * NT_;

    if (tid < NT_)
        bias_s[tid] = (n0 < DO_) ? bq[n0 + tid] : bv[n0 - DO_ + tid];

    // ---- A loader setup: thread owns row (tid&127), k-half (tid>>7)
    const int arow = tid & 127;
    const int ahalf = tid >> 7;      // 0 or 1 (16 k-elems each)
    const int r_g  = m0 + arow;
    bool a_valid;
    const float* a_src;
    {
        int bb = r_g / TP_;
        int tp = r_g - bb * TP_;
        if (r_g < ROWS_) {
            a_valid = (tp >= W1_) && (tp < W1_ + T_);
            a_src = a_valid ? inputs + ((size_t)bb * T_ + (tp - W1_)) * D_ : inputs;
        } else if (r_g < MTOT_) {
            a_valid = true;
            a_src = pos_emb + (size_t)(r_g - ROWS_) * D_;
        } else {
            a_valid = false;
            a_src = inputs;
        }
    }

    const int mwarp = wid >> 2;      // 0..1 (64 rows)
    const int nwarp = wid & 3;       // 0..3 (32 cols)
    const int fg = lane >> 2;        // fragment row/col group 0..7
    const int fc = (lane & 3) * 2;   // fragment k/col pair base

    float acc[4][4][4];
    #pragma unroll
    for (int mt = 0; mt < 4; mt++)
        #pragma unroll
        for (int nt = 0; nt < 4; nt++)
            #pragma unroll
            for (int e = 0; e < 4; e++) acc[mt][nt][e] = 0.f;

    for (int c = 0; c < NCHUNK_; c++) {
        // ---- A: load 16 fp32, split hi/lo, store to smem (conflict-free)
        #pragma unroll
        for (int g = 0; g < 2; g++) {
            float v[8];
            if (a_valid) {
                const float* p = a_src + c * CHUNK_ + ahalf * 16 + g * 8;
                float4 f0 = *(const float4*)p;
                float4 f1 = *(const float4*)(p + 4);
                v[0]=f0.x; v[1]=f0.y; v[2]=f0.z; v[3]=f0.w;
                v[4]=f1.x; v[5]=f1.y; v[6]=f1.z; v[7]=f1.w;
            } else {
                #pragma unroll
                for (int i = 0; i < 8; i++) v[i] = 0.f;
            }
            uint32_t hp[4], lp[4];
            #pragma unroll
            for (int i = 0; i < 4; i++) {
                __nv_bfloat16 h0 = __float2bfloat16(v[2*i]);
                __nv_bfloat16 h1 = __float2bfloat16(v[2*i+1]);
                float l0 = v[2*i]   - __bfloat162float(h0);
                float l1 = v[2*i+1] - __bfloat162float(h1);
                __nv_bfloat16 e0 = __float2bfloat16(l0);
                __nv_bfloat16 e1 = __float2bfloat16(l1);
                hp[i] = (uint32_t)__bfloat16_as_ushort(h0)
                      | ((uint32_t)__bfloat16_as_ushort(h1) << 16);
                lp[i] = (uint32_t)__bfloat16_as_ushort(e0)
                      | ((uint32_t)__bfloat16_as_ushort(e1) << 16);
            }
            int off = arow * ASTRIDE_ + ahalf * 16 + g * 8;   // elems, 16B aligned
            *(uint4*)&sAh[off] = make_uint4(hp[0], hp[1], hp[2], hp[3]);
            *(uint4*)&sAl[off] = make_uint4(lp[0], lp[1], lp[2], lp[3]);
        }
        // ---- B: copy pre-split bf16 (128 n-rows x 32 k)
        #pragma unroll
        for (int i = 0; i < 2; i++) {
            int u = tid + i * 256;           // 16B unit, 0..511
            int brow = u >> 2;
            int bu   = u & 3;
            size_t gi = (size_t)(n0 + brow) * D_ + c * CHUNK_ + bu * 8;
            uint4 hv = *(const uint4*)(g_bhi + gi);
            uint4 lv = *(const uint4*)(g_blo + gi);
            int off = brow * ASTRIDE_ + bu * 8;
            *(uint4*)&sBh[off] = hv;
            *(uint4*)&sBl[off] = lv;
        }
        __syncthreads();

        // ---- MMA: 2 k16 steps x 3 products x 16 tiles
        #pragma unroll
        for (int ks = 0; ks < 2; ks++) {
            const int k0 = ks * 16;
            uint32_t Ah[4][4], Bh[4][2];
            #pragma unroll
            for (int mt = 0; mt < 4; mt++) {
                int r = mwarp * 64 + mt * 16 + fg;
                Ah[mt][0] = *(const uint32_t*)&sAh[r * ASTRIDE_ + k0 + fc];
                Ah[mt][1] = *(const uint32_t*)&sAh[(r + 8) * ASTRIDE_ + k0 + fc];
                Ah[mt][2] = *(const uint32_t*)&sAh[r * ASTRIDE_ + k0 + fc + 8];
                Ah[mt][3] = *(const uint32_t*)&sAh[(r + 8) * ASTRIDE_ + k0 + fc + 8];
            }
            #pragma unroll
            for (int nt = 0; nt < 4; nt++) {
                int n = nwarp * 32 + nt * 8 + fg;
                Bh[nt][0] = *(const uint32_t*)&sBh[n * ASTRIDE_ + k0 + fc];
                Bh[nt][1] = *(const uint32_t*)&sBh[n * ASTRIDE_ + k0 + fc + 8];
            }
            #pragma unroll
            for (int mt = 0; mt < 4; mt++)
                #pragma unroll
                for (int nt = 0; nt < 4; nt++)
                    mma_bf16(acc[mt][nt], Ah[mt], Bh[nt]);

            uint32_t Al[4][4];
            #pragma unroll
            for (int mt = 0; mt < 4; mt++) {
                int r = mwarp * 64 + mt * 16 + fg;
                Al[mt][0] = *(const uint32_t*)&sAl[r * ASTRIDE_ + k0 + fc];
                Al[mt][1] = *(const uint32_t*)&sAl[(r + 8) * ASTRIDE_ + k0 + fc];
                Al[mt][2] = *(const uint32_t*)&sAl[r * ASTRIDE_ + k0 + fc + 8];
                Al[mt][3] = *(const uint32_t*)&sAl[(r + 8) * ASTRIDE_ + k0 + fc + 8];
            }
            #pragma unroll
            for (int mt = 0; mt < 4; mt++)
                #pragma unroll
                for (int nt = 0; nt < 4; nt++)
                    mma_bf16(acc[mt][nt], Al[mt], Bh[nt]);

            uint32_t Bl[4][2];
            #pragma unroll
            for (int nt = 0; nt < 4; nt++) {
                int n = nwarp * 32 + nt * 8 + fg;
                Bl[nt][0] = *(const uint32_t*)&sBl[n * ASTRIDE_ + k0 + fc];
                Bl[nt][1] = *(const uint32_t*)&sBl[n * ASTRIDE_ + k0 + fc + 8];
            }
            #pragma unroll
            for (int mt = 0; mt < 4; mt++)
                #pragma unroll
                for (int nt = 0; nt < 4; nt++)
                    mma_bf16(acc[mt][nt], Ah[mt], Bl[nt]);
        }
        __syncthreads();
    }

    // ---- epilogue: d0/d1 -> (row fg, cols fc,fc+1); d2/d3 -> row fg+8
    const int colbase = n0 + nwarp * 32;
    #pragma unroll
    for (int mt = 0; mt < 4; mt++) {
        #pragma unroll
        for (int rh = 0; rh < 2; rh++) {
            int r = m0 + mwarp * 64 + mt * 16 + fg + rh * 8;
            float* dst;
            bool add_bias;
            if (r < ROWS_) {
                dst = g_qv + (size_t)r * NQV_ + colbase;
                add_bias = true;
            } else if (r < MTOT_) {
                dst = g_pos + (size_t)(r - ROWS_) * NQV_ + colbase;
                add_bias = false;
            } else continue;
            #pragma unroll
            for (int nt = 0; nt < 4; nt++) {
                int cidx = nwarp * 32 + nt * 8 + fc;
                float2 o;
                o.x = acc[mt][nt][rh * 2];
                o.y = acc[mt][nt][rh * 2 + 1];
                if (add_bias) { o.x += bias_s[cidx]; o.y += bias_s[cidx + 1]; }
                *(float2*)(dst + nt * 8 + fc) = o;
            }
        }
    }
}

// ---------------------------------------------------------------------------
// Sliding-window score/context (unchanged).
// ---------------------------------------------------------------------------
__global__ __launch_bounds__(256) void attn_kernel(float* __restrict__ out) {
    __shared__ float ks[78 * 64];
    __shared__ float vs[78 * 64];
    __shared__ float pq[W2_ * 64];
    __shared__ float pv[W2_ * 64];

    const int bx    = blockIdx.x;          // 0..511
    const int chunk = bx & 63;
    const int h     = (bx >> 6) & 3;
    const int b     = bx >> 8;
    const int t0    = chunk * 64;
    const int tid   = threadIdx.x;

    const size_t base_row = (size_t)b * TP_ + t0;   // padded coords

    for (int idx = tid; idx < 78 * 16; idx += 256) {
        int row = idx >> 4, c4 = idx & 15;
        const float* src = g_qv + (base_row + row) * NQV_ + h * DH_;
        ((float4*)ks)[row * 16 + c4] = ((const float4*)src)[c4];
        ((float4*)vs)[row * 16 + c4] = ((const float4*)(src + DO_))[c4];
    }
    for (int idx = tid; idx < W2_ * 16; idx += 256) {
        int row = idx >> 4, c4 = idx & 15;
        const float* src = g_pos + (size_t)row * NQV_ + h * DH_;
        ((float4*)pq)[row * 16 + c4] = ((const float4*)src)[c4];
        ((float4*)pv)[row * 16 + c4] = ((const float4*)(src + DO_))[c4];
    }
    __syncthreads();

    const int warp = tid >> 5;
    const int lane = tid & 31;

    for (int j = 0; j < 8; j++) {
        const int tl = warp * 8 + j;   // 0..63
        const float q0 = ks[(tl + W1_) * 64 + lane];
        const float q1 = ks[(tl + W1_) * 64 + lane + 32];

        float p[W2_];
        #pragma unroll
        for (int w = 0; w < W2_; w++) {
            float k0 = ks[(tl + w) * 64 + lane]      + pq[w * 64 + lane];
            float k1 = ks[(tl + w) * 64 + lane + 32] + pq[w * 64 + lane + 32];
            p[w] = q0 * k0 + q1 * k1;
        }
        #pragma unroll
        for (int off = 16; off >= 1; off >>= 1) {
            #pragma unroll
            for (int w = 0; w < W2_; w++)
                p[w] += __shfl_xor_sync(0xffffffffu, p[w], off);
        }
        float a0 = 0.f, a1 = 0.f;
        #pragma unroll
        for (int w = 0; w < W2_; w++) {
            a0 += p[w] * (vs[(tl + w) * 64 + lane]      + pv[w * 64 + lane]);
            a1 += p[w] * (vs[(tl + w) * 64 + lane + 32] + pv[w * 64 + lane + 32]);
        }
        const int t = t0 + tl;
        float* dst = out + ((size_t)b * T_ + t) * DO_ + h * DH_;
        dst[lane]      = a0;
        dst[lane + 32] = a1;
    }
}

// ---------------------------------------------------------------------------
extern "C" void kernel_launch(void* const* d_in, const int* in_sizes, int n_in,
                              void* d_out, int out_size) {
    const float* inputs  = (const float*)d_in[0];
    const float* Wq      = (const float*)d_in[1];
    const float* bq      = (const float*)d_in[2];
    const float* Wv      = (const float*)d_in[3];
    const float* bv      = (const float*)d_in[4];
    const float* pos_emb = (const float*)d_in[5];
    float* out = (float*)d_out;

    bprep_kernel<<<(NQV_ * D_ + 255) / 256, 256>>>(Wq, Wv);

    dim3 ggrid((MTOT_ + MT_ - 1) / MT_, NQV_ / NT_);
    gemm_mma_kernel<<<ggrid, 256>>>(inputs, bq, bv, pos_emb);

    attn_kernel<<<B_ * H_ * (T_ / 64), 256>>>(out);
}

// round 5
// speedup vs baseline: 2.5076x; 1.3205x over previous
#include <cuda_runtime.h>
#include <cuda_bf16.h>
#include <cstdint>

// Problem constants
#define B_   2
#define T_   4096
#define D_   768
#define DO_  256
#define H_   4
#define DH_  64
#define W1_  7
#define W2_  15
#define TP_  (T_ + 2*W1_)       // 4110
#define ROWS_ (B_ * TP_)        // 8220
#define MTOT_ (ROWS_ + W2_)     // 8235
#define MPAD_ 8320              // 65 * 128
#define NQV_ 512

#define MT_ 128
#define NT_ 128
#define KC_ 32                  // k per chunk
#define NCHUNK_ (D_ / KC_)      // 24
#define ASTR_ 40                // bf16 elems per smem row (32 + 8 pad)

// smem stage layout (bytes): Ah[0,10240) Al[10240) Bh[20480) Bl[30720), stage=40960
#define STG_B_ 40960
#define GSMEM_ (2 * STG_B_)     // 81920

// Scratch
__device__ float g_qv[ROWS_ * NQV_];
__device__ float g_pos[W2_ * NQV_];
__device__ __nv_bfloat16 g_ahi[MPAD_ * D_];
__device__ __nv_bfloat16 g_alo[MPAD_ * D_];
__device__ __nv_bfloat16 g_bhi[NQV_ * D_];
__device__ __nv_bfloat16 g_blo[NQV_ * D_];

// ---------------------------------------------------------------------------
__device__ __forceinline__ uint32_t smem_u32(const void* p) {
    uint32_t a;
    asm("{ .reg .u64 t; cvta.to.shared.u64 t, %1; cvt.u32.u64 %0, t; }"
        : "=r"(a) : "l"(p));
    return a;
}
#define CPA16(dst, src) \
    asm volatile("cp.async.ca.shared.global [%0], [%1], 16;" :: "r"(dst), "l"(src))
#define CPA_COMMIT() asm volatile("cp.async.commit_group;" ::: "memory")
#define CPA_WAIT(n)  asm volatile("cp.async.wait_group %0;" :: "n"(n) : "memory")
#define LDMX4(r0, r1, r2, r3, a) \
    asm volatile("ldmatrix.sync.aligned.m8n8.x4.shared.b16 {%0,%1,%2,%3}, [%4];" \
                 : "=r"(r0), "=r"(r1), "=r"(r2), "=r"(r3) : "r"(a))

__device__ __forceinline__ void mma_bf16(float* d, const uint32_t* a,
                                         const uint32_t* b) {
    asm volatile(
        "mma.sync.aligned.m16n8k16.row.col.f32.bf16.bf16.f32 "
        "{%0,%1,%2,%3}, {%4,%5,%6,%7}, {%8,%9}, {%0,%1,%2,%3};"
        : "+f"(d[0]), "+f"(d[1]), "+f"(d[2]), "+f"(d[3])
        : "r"(a[0]), "r"(a[1]), "r"(a[2]), "r"(a[3]), "r"(b[0]), "r"(b[1]));
}

// ---------------------------------------------------------------------------
// Prep: split weights AND activations (+pos, +zero pad) into bf16 hi/lo.
// Vector slot = 8 contiguous k. Weights first (512*96 slots), then A rows
// (8320*96 slots).
// ---------------------------------------------------------------------------
#define NWV_ (NQV_ * (D_ / 8))          // 49152
#define NAV_ (MPAD_ * (D_ / 8))         // 798720
__global__ void prep_kernel(const float* __restrict__ inputs,
                            const float* __restrict__ Wq,
                            const float* __restrict__ Wv,
                            const float* __restrict__ pos_emb) {
    int i = blockIdx.x * blockDim.x + threadIdx.x;
    const float* src = nullptr;
    __nv_bfloat16 *dhi, *dlo;
    size_t off;
    if (i < NWV_) {
        int n = i >> 6; n /= (D_ / 8 / 64);   // avoid div cost? keep simple:
        n = i / (D_ / 8);
        int k8 = (i - n * (D_ / 8)) * 8;
        src = (n < DO_) ? Wq + (size_t)n * D_ + k8
                        : Wv + (size_t)(n - DO_) * D_ + k8;
        off = (size_t)n * D_ + k8;
        dhi = g_bhi; dlo = g_blo;
    } else if (i < NWV_ + NAV_) {
        int j = i - NWV_;
        int r = j / (D_ / 8);
        int k8 = (j - r * (D_ / 8)) * 8;
        off = (size_t)r * D_ + k8;
        dhi = g_ahi; dlo = g_alo;
        if (r < ROWS_) {
            int bb = r / TP_;
            int tp = r - bb * TP_;
            if (tp >= W1_ && tp < W1_ + T_)
                src = inputs + ((size_t)bb * T_ + (tp - W1_)) * D_ + k8;
        } else if (r < MTOT_) {
            src = pos_emb + (size_t)(r - ROWS_) * D_ + k8;
        }
    } else return;

    uint32_t hp[4], lp[4];
    if (src) {
        float4 f0 = *(const float4*)src;
        float4 f1 = *(const float4*)(src + 4);
        float v[8] = {f0.x, f0.y, f0.z, f0.w, f1.x, f1.y, f1.z, f1.w};
        #pragma unroll
        for (int e = 0; e < 4; e++) {
            __nv_bfloat16 h0 = __float2bfloat16(v[2*e]);
            __nv_bfloat16 h1 = __float2bfloat16(v[2*e+1]);
            __nv_bfloat16 l0 = __float2bfloat16(v[2*e]   - __bfloat162float(h0));
            __nv_bfloat16 l1 = __float2bfloat16(v[2*e+1] - __bfloat162float(h1));
            hp[e] = (uint32_t)__bfloat16_as_ushort(h0)
                  | ((uint32_t)__bfloat16_as_ushort(h1) << 16);
            lp[e] = (uint32_t)__bfloat16_as_ushort(l0)
                  | ((uint32_t)__bfloat16_as_ushort(l1) << 16);
        }
    } else {
        #pragma unroll
        for (int e = 0; e < 4; e++) { hp[e] = 0u; lp[e] = 0u; }
    }
    *(uint4*)(dhi + off) = make_uint4(hp[0], hp[1], hp[2], hp[3]);
    *(uint4*)(dlo + off) = make_uint4(lp[0], lp[1], lp[2], lp[3]);
}

// ---------------------------------------------------------------------------
// GEMM [8320, 768] x [512, 768]^T, 3-term bf16 split, HMMA + cp.async + LDSM.
// CTA 128x128, 8 warps (2x4), warp 64x32, double-buffered k=32 chunks.
// ---------------------------------------------------------------------------
extern __shared__ __align__(16) char gsm[];

__global__ __launch_bounds__(256, 2) void gemm_mma_kernel(
    const float* __restrict__ bq, const float* __restrict__ bv)
{
    __shared__ float bias_s[NT_];
    const uint32_t smb = smem_u32(gsm);
    const int tid  = threadIdx.x;
    const int wid  = tid >> 5;
    const int lane = tid & 31;
    const int m0   = blockIdx.x * MT_;
    const int n0   = blockIdx.y * NT_;

    if (tid < NT_)
        bias_s[tid] = (n0 < DO_) ? bq[n0 + tid] : bv[n0 - DO_ + tid];

    // loader indices: unit u covers (row = u>>2, ku = u&3), u in [0,512)
    const int u0row = tid >> 2, u0ku = tid & 3;          // u = tid
    const int u1row = (tid + 256) >> 2, u1ku = u0ku;     // u = tid + 256

    const __nv_bfloat16* srcA0h = g_ahi + (size_t)(m0 + u0row) * D_ + u0ku * 8;
    const __nv_bfloat16* srcA0l = g_alo + (size_t)(m0 + u0row) * D_ + u0ku * 8;
    const __nv_bfloat16* srcA1h = g_ahi + (size_t)(m0 + u1row) * D_ + u1ku * 8;
    const __nv_bfloat16* srcA1l = g_alo + (size_t)(m0 + u1row) * D_ + u1ku * 8;
    const __nv_bfloat16* srcB0h = g_bhi + (size_t)(n0 + u0row) * D_ + u0ku * 8;
    const __nv_bfloat16* srcB0l = g_blo + (size_t)(n0 + u0row) * D_ + u0ku * 8;
    const __nv_bfloat16* srcB1h = g_bhi + (size_t)(n0 + u1row) * D_ + u1ku * 8;
    const __nv_bfloat16* srcB1l = g_blo + (size_t)(n0 + u1row) * D_ + u1ku * 8;
    const uint32_t d0 = (uint32_t)(u0row * ASTR_ + u0ku * 8) * 2;
    const uint32_t d1 = (uint32_t)(u1row * ASTR_ + u1ku * 8) * 2;

    #define ISSUE_CHUNK(c, s) do {                                   \
        uint32_t st = smb + (s) * STG_B_;                            \
        int kk = (c) * KC_;                                          \
        CPA16(st + d0,          srcA0h + kk);                        \
        CPA16(st + d1,          srcA1h + kk);                        \
        CPA16(st + 10240 + d0,  srcA0l + kk);                        \
        CPA16(st + 10240 + d1,  srcA1l + kk);                        \
        CPA16(st + 20480 + d0,  srcB0h + kk);                        \
        CPA16(st + 20480 + d1,  srcB1h + kk);                        \
        CPA16(st + 30720 + d0,  srcB0l + kk);                        \
        CPA16(st + 30720 + d1,  srcB1l + kk);                        \
        CPA_COMMIT();                                                \
    } while (0)

    // fragment address bases (bytes into stage)
    const int mwarp = wid >> 2, nwarp = wid & 3;
    const uint32_t aBase = (uint32_t)(((mwarp * 64 + (lane & 15)) * ASTR_
                                      + ((lane >> 4) * 8)) * 2);
    const uint32_t bBase = (uint32_t)(((nwarp * 32 + (lane & 7)
                                      + ((lane >> 4) & 1) * 8) * ASTR_
                                      + (((lane >> 3) & 1) * 8)) * 2) + 20480;

    float acc[4][4][4];
    #pragma unroll
    for (int mt = 0; mt < 4; mt++)
        #pragma unroll
        for (int nt = 0; nt < 4; nt++)
            #pragma unroll
            for (int e = 0; e < 4; e++) acc[mt][nt][e] = 0.f;

    ISSUE_CHUNK(0, 0);

    for (int c = 0; c < NCHUNK_; c++) {
        if (c + 1 < NCHUNK_) {
            ISSUE_CHUNK(c + 1, (c + 1) & 1);
            CPA_WAIT(1);
        } else {
            CPA_WAIT(0);
        }
        __syncthreads();

        const uint32_t st = smb + (c & 1) * STG_B_;
        #pragma unroll
        for (int ks = 0; ks < 2; ks++) {
            const uint32_t ko = ks * 32;   // 16 elems * 2B
            uint32_t Ah[4][4], Bh[2][4], Al[4][4], Bl[2][4];
            #pragma unroll
            for (int mt = 0; mt < 4; mt++)
                LDMX4(Ah[mt][0], Ah[mt][1], Ah[mt][2], Ah[mt][3],
                      st + aBase + mt * (16 * ASTR_ * 2) + ko);
            #pragma unroll
            for (int pr = 0; pr < 2; pr++)
                LDMX4(Bh[pr][0], Bh[pr][1], Bh[pr][2], Bh[pr][3],
                      st + bBase + pr * (16 * ASTR_ * 2) + ko);
            #pragma unroll
            for (int mt = 0; mt < 4; mt++)
                #pragma unroll
                for (int nt = 0; nt < 4; nt++)
                    mma_bf16(acc[mt][nt], Ah[mt], &Bh[nt >> 1][(nt & 1) * 2]);

            #pragma unroll
            for (int mt = 0; mt < 4; mt++)
                LDMX4(Al[mt][0], Al[mt][1], Al[mt][2], Al[mt][3],
                      st + aBase + 10240 + mt * (16 * ASTR_ * 2) + ko);
            #pragma unroll
            for (int mt = 0; mt < 4; mt++)
                #pragma unroll
                for (int nt = 0; nt < 4; nt++)
                    mma_bf16(acc[mt][nt], Al[mt], &Bh[nt >> 1][(nt & 1) * 2]);

            #pragma unroll
            for (int pr = 0; pr < 2; pr++)
                LDMX4(Bl[pr][0], Bl[pr][1], Bl[pr][2], Bl[pr][3],
                      st + bBase + 10240 + pr * (16 * ASTR_ * 2) + ko);
            #pragma unroll
            for (int mt = 0; mt < 4; mt++)
                #pragma unroll
                for (int nt = 0; nt < 4; nt++)
                    mma_bf16(acc[mt][nt], Ah[mt], &Bl[nt >> 1][(nt & 1) * 2]);
        }
        __syncthreads();
    }

    // epilogue
    const int fg = lane >> 2;
    const int fc = (lane & 3) * 2;
    const int colbase = n0 + nwarp * 32;
    #pragma unroll
    for (int mt = 0; mt < 4; mt++) {
        #pragma unroll
        for (int rh = 0; rh < 2; rh++) {
            int r = m0 + mwarp * 64 + mt * 16 + fg + rh * 8;
            float* dst;
            bool add_bias;
            if (r < ROWS_) {
                dst = g_qv + (size_t)r * NQV_ + colbase;
                add_bias = true;
            } else if (r < MTOT_) {
                dst = g_pos + (size_t)(r - ROWS_) * NQV_ + colbase;
                add_bias = false;
            } else continue;
            #pragma unroll
            for (int nt = 0; nt < 4; nt++) {
                int cidx = nwarp * 32 + nt * 8 + fc;
                float2 o;
                o.x = acc[mt][nt][rh * 2];
                o.y = acc[mt][nt][rh * 2 + 1];
                if (add_bias) { o.x += bias_s[cidx]; o.y += bias_s[cidx + 1]; }
                *(float2*)(dst + nt * 8 + fc) = o;
            }
        }
    }
}

// ---------------------------------------------------------------------------
// Attn v2: block = 64 t for one (b,h); warp covers 8 t in parallel
// (lane = 4*tsub + dg; dg owns 16 dims). Padded layout: row stride 80 floats,
// dim-group stride 20 -> conflict-free LDS.128. 2 shfl per (t,w) reduction.
// ---------------------------------------------------------------------------
#define RST_ 80
#define ATT_SMEM_ ((78 * RST_ * 2 + W2_ * RST_ * 2) * 4)   // 59520 B

extern __shared__ __align__(16) float asmf[];

__global__ __launch_bounds__(256) void attn_kernel(float* __restrict__ out) {
    float* ks = asmf;
    float* vs = ks + 78 * RST_;
    float* pq = vs + 78 * RST_;
    float* pv = pq + W2_ * RST_;

    const int bx    = blockIdx.x;
    const int chunk = bx & 63;
    const int h     = (bx >> 6) & 3;
    const int b     = bx >> 8;
    const int t0    = chunk * 64;
    const int tid   = threadIdx.x;

    const size_t base_row = (size_t)b * TP_ + t0;

    for (int idx = tid; idx < 78 * 16; idx += 256) {
        int row = idx >> 4, c4 = idx & 15;
        int doff = row * RST_ + (c4 >> 2) * 20 + (c4 & 3) * 4;
        const float* src = g_qv + (base_row + row) * NQV_ + h * DH_ + c4 * 4;
        *(float4*)(ks + doff) = *(const float4*)src;
        *(float4*)(vs + doff) = *(const float4*)(src + DO_);
    }
    for (int idx = tid; idx < W2_ * 16; idx += 256) {
        int row = idx >> 4, c4 = idx & 15;
        int doff = row * RST_ + (c4 >> 2) * 20 + (c4 & 3) * 4;
        const float* src = g_pos + (size_t)row * NQV_ + h * DH_ + c4 * 4;
        *(float4*)(pq + doff) = *(const float4*)src;
        *(float4*)(pv + doff) = *(const float4*)(src + DO_);
    }
    __syncthreads();

    const int warp = tid >> 5;
    const int lane = tid & 31;
    const int tsub = lane >> 2;
    const int dg   = lane & 3;
    const int tl   = warp * 8 + tsub;
    const int dgo  = dg * 20;

    // q: 16 dims of row tl+7
    float4 q[4];
    #pragma unroll
    for (int j = 0; j < 4; j++)
        q[j] = *(const float4*)(ks + (tl + W1_) * RST_ + dgo + j * 4);

    float4 a4[4];
    #pragma unroll
    for (int j = 0; j < 4; j++) a4[j] = make_float4(0.f, 0.f, 0.f, 0.f);

    #pragma unroll
    for (int w = 0; w < W2_; w++) {
        const float* kr = ks + (tl + w) * RST_ + dgo;
        const float* pr = pq + w * RST_ + dgo;
        float p0 = 0.f, p1 = 0.f, p2 = 0.f, p3 = 0.f;
        {
            float4 kv0 = *(const float4*)(kr);
            float4 pv0 = *(const float4*)(pr);
            p0 = q[0].x*(kv0.x+pv0.x) + q[0].y*(kv0.y+pv0.y)
               + q[0].z*(kv0.z+pv0.z) + q[0].w*(kv0.w+pv0.w);
            float4 kv1 = *(const float4*)(kr + 4);
            float4 pv1 = *(const float4*)(pr + 4);
            p1 = q[1].x*(kv1.x+pv1.x) + q[1].y*(kv1.y+pv1.y)
               + q[1].z*(kv1.z+pv1.z) + q[1].w*(kv1.w+pv1.w);
            float4 kv2 = *(const float4*)(kr + 8);
            float4 pv2 = *(const float4*)(pr + 8);
            p2 = q[2].x*(kv2.x+pv2.x) + q[2].y*(kv2.y+pv2.y)
               + q[2].z*(kv2.z+pv2.z) + q[2].w*(kv2.w+pv2.w);
            float4 kv3 = *(const float4*)(kr + 12);
            float4 pv3 = *(const float4*)(pr + 12);
            p3 = q[3].x*(kv3.x+pv3.x) + q[3].y*(kv3.y+pv3.y)
               + q[3].z*(kv3.z+pv3.z) + q[3].w*(kv3.w+pv3.w);
        }
        float p = (p0 + p1) + (p2 + p3);
        p += __shfl_xor_sync(0xffffffffu, p, 1);
        p += __shfl_xor_sync(0xffffffffu, p, 2);

        const float* vr = vs + (tl + w) * RST_ + dgo;
        const float* pw = pv + w * RST_ + dgo;
        #pragma unroll
        for (int j = 0; j < 4; j++) {
            float4 vv = *(const float4*)(vr + j * 4);
            float4 pp = *(const float4*)(pw + j * 4);
            a4[j].x += p * (vv.x + pp.x);
            a4[j].y += p * (vv.y + pp.y);
            a4[j].z += p * (vv.z + pp.z);
            a4[j].w += p * (vv.w + pp.w);
        }
    }

    const int t = t0 + tl;
    float* dst = out + ((size_t)b * T_ + t) * DO_ + h * DH_ + dg * 16;
    #pragma unroll
    for (int j = 0; j < 4; j++)
        *(float4*)(dst + j * 4) = a4[j];
}

// ---------------------------------------------------------------------------
extern "C" void kernel_launch(void* const* d_in, const int* in_sizes, int n_in,
                              void* d_out, int out_size) {
    const float* inputs  = (const float*)d_in[0];
    const float* Wq      = (const float*)d_in[1];
    const float* bq      = (const float*)d_in[2];
    const float* Wv      = (const float*)d_in[3];
    const float* bv      = (const float*)d_in[4];
    const float* pos_emb = (const float*)d_in[5];
    float* out = (float*)d_out;

    cudaFuncSetAttribute(gemm_mma_kernel,
                         cudaFuncAttributeMaxDynamicSharedMemorySize, GSMEM_);
    cudaFuncSetAttribute(attn_kernel,
                         cudaFuncAttributeMaxDynamicSharedMemorySize, ATT_SMEM_);

    prep_kernel<<<(NWV_ + NAV_ + 255) / 256, 256>>>(inputs, Wq, Wv, pos_emb);

    dim3 ggrid(MPAD_ / MT_, NQV_ / NT_);
    gemm_mma_kernel<<<ggrid, 256, GSMEM_>>>(bq, bv);

    attn_kernel<<<B_ * H_ * (T_ / 64), 256, ATT_SMEM_>>>(out);
}